// round 14
// baseline (speedup 1.0000x reference)
#include <cuda_runtime.h>
#include <cuda_fp16.h>
#include <mma.h>
#include <math.h>
#include <stdint.h>

using namespace nvcuda;

#define HW   4096
#define WD   64
#define C    256
#define B    16
#define NO   260   // 256 ctx channels + 4 gate channels

// ---------------- scratch (static device globals; no allocs) ----------------
__device__ float g_t[B * NO * HW];       // conv1x1 output: ctx(256, no bias) + gates(4, biased)
__device__ float g_ctxall[B * C * HW];   // ctx_all
__device__ float g_klog[B * HW];
__device__ float g_k[B * HW];
__device__ float g_qk[B * C];
__device__ float g_v[B * C];
__device__ __align__(16) __half g_wh[C * C];   // w in fp16 (ctx rows)

// ---------------- cp.async helpers -----------------------------------------
__device__ __forceinline__ unsigned s2u(const void* p) {
    return (unsigned)__cvta_generic_to_shared(p);
}
__device__ __forceinline__ void cp16(unsigned dst, const void* src) {
    asm volatile("cp.async.ca.shared.global [%0], [%1], 16;" :: "r"(dst), "l"(src));
}
#define CP_COMMIT() asm volatile("cp.async.commit_group;")
#define CP_WAIT1()  asm volatile("cp.async.wait_group 1;")

// =====================================================================
// K0: convert w (ctx rows 0..255) to fp16
// =====================================================================
__global__ __launch_bounds__(256) void k_whalf(const float* __restrict__ w) {
    int idx = blockIdx.x * 256 + threadIdx.x;   // grid 256 -> 65536
    g_wh[idx] = __float2half(w[idx]);
}

// =====================================================================
// K1: wmma fp16 GEMM (SINGLE product — fp16's 11-bit mantissa keeps
// norm rel-err ~1e-4, 10x inside the 1e-3 budget), in-kernel x->fp16
// conversion, + FUSED gate outputs (o=256..259) on oh==0 CTAs.
// SMEM buffer (half elems): A 128x40=5120 | B 32x136=4352  -> 18.9KB x2
// =====================================================================
#define BUF_ELEMS 9472
#define OFF_B 5120
#define GEMM_SMEM (2 * BUF_ELEMS * 2)   // 37888 bytes

__global__ __launch_bounds__(256, 3) void k_gemm(const float* __restrict__ x,
                                                 const float* __restrict__ w,
                                                 const float* __restrict__ bias) {
    extern __shared__ __align__(16) __half sm[];
    __shared__ float sgw[C][4];
    const int tid = threadIdx.x;
    const int wid = tid >> 5;
    const int bx = blockIdx.x;
    const int pw = bx & 31, oh = (bx >> 5) & 1, b = bx >> 6;
    const int px0 = pw << 7, o0 = oh << 7;
    const int wm = wid & 1, wn = wid >> 1;   // warp tile 64x32

    wmma::fragment<wmma::accumulator, 16, 16, 16, float> acc[4][2];
#pragma unroll
    for (int i = 0; i < 4; i++)
#pragma unroll
        for (int j = 0; j < 2; j++) wmma::fill_fragment(acc[i][j], 0.f);

    float4 gacc[4];
#pragma unroll
    for (int j = 0; j < 4; j++) gacc[j] = make_float4(0.f, 0.f, 0.f, 0.f);
    if (oh == 0) {
#pragma unroll
        for (int it = 0; it < 4; it++) {
            int i = tid + it * 256;
            sgw[i >> 2][i & 3] = w[(256 + (i & 3)) * C + (i >> 2)];
        }
    }

    auto stageA = [&](int ci) {
        unsigned base = s2u(sm + (ci & 1) * BUF_ELEMS);
        const int k0 = ci << 5;
#pragma unroll
        for (int it = 0; it < 2; it++) {
            int idx = tid + it * 256;            // 0..511: 128o x 4 groups of 8 halfs
            int o = idx >> 2, u = idx & 3;
            cp16(base + (unsigned)((o * 40 + u * 8) * 2),
                 g_wh + (o0 + o) * 256 + k0 + u * 8);
        }
    };
    auto ldx = [&](float4* R, int ci) {
        const int k0 = ci << 5;
#pragma unroll
        for (int it = 0; it < 4; it++) {
            int fi = it * 256 + tid;
            int k = fi >> 5, u = fi & 31;
            R[it] = *(const float4*)(x + (((size_t)(b * C + k0 + k)) << 12) + px0 + u * 4);
        }
    };
    auto stsB = [&](const float4* R, int ci) {
        __half* bp = sm + (ci & 1) * BUF_ELEMS;
#pragma unroll
        for (int it = 0; it < 4; it++) {
            int fi = it * 256 + tid;
            int k = fi >> 5, u = fi & 31;
            float4 v = R[it];
            __half2 h0 = __floats2half2_rn(v.x, v.y);
            __half2 h1 = __floats2half2_rn(v.z, v.w);
            uint2 hv = {*(uint32_t*)&h0, *(uint32_t*)&h1};
            *(uint2*)(bp + OFF_B + k * 136 + u * 4) = hv;
            if (oh == 0) {
                int c = (ci << 5) + k;
#pragma unroll
                for (int j = 0; j < 4; j++) {
                    float gw = sgw[c][j];
                    gacc[j].x = fmaf(gw, v.x, gacc[j].x);
                    gacc[j].y = fmaf(gw, v.y, gacc[j].y);
                    gacc[j].z = fmaf(gw, v.z, gacc[j].z);
                    gacc[j].w = fmaf(gw, v.w, gacc[j].w);
                }
            }
        }
    };
    auto compute = [&](int ci) {
        const __half* bufp = sm + (ci & 1) * BUF_ELEMS;
        const __half* A = bufp;
        const __half* Bt = bufp + OFF_B;
#pragma unroll
        for (int kk = 0; kk < 2; kk++) {
            wmma::fragment<wmma::matrix_a, 16, 16, 16, __half, wmma::row_major> af[4];
            wmma::fragment<wmma::matrix_b, 16, 16, 16, __half, wmma::row_major> bf[2];
#pragma unroll
            for (int j = 0; j < 2; j++)
                wmma::load_matrix_sync(bf[j], Bt + kk * 16 * 136 + wn * 32 + j * 16, 136);
#pragma unroll
            for (int i = 0; i < 4; i++)
                wmma::load_matrix_sync(af[i], A + (wm * 64 + i * 16) * 40 + kk * 16, 40);
#pragma unroll
            for (int i = 0; i < 4; i++)
#pragma unroll
                for (int j = 0; j < 2; j++)
                    wmma::mma_sync(acc[i][j], af[i], bf[j], acc[i][j]);
        }
    };

    float4 R[4];
    stageA(0);
    CP_COMMIT();
    ldx(R, 0);
    __syncthreads();
    for (int ci = 0; ci < 8; ci++) {
        if (ci < 7) stageA(ci + 1);
        CP_COMMIT();
        CP_WAIT1();
        stsB(R, ci);
        __syncthreads();
        if (ci < 7) ldx(R, ci + 1);
        compute(ci);
        __syncthreads();
    }

    // ---- gate reduce + store (oh==0 only; smem buffer is dead now) ----
    if (oh == 0) {
        float* gp = (float*)sm;
#pragma unroll
        for (int j = 0; j < 4; j++)
            *(float4*)(gp + tid * 16 + j * 4) = gacc[j];
        __syncthreads();
#pragma unroll
        for (int t = 0; t < 2; t++) {
            int o = tid + t * 256;
            int u = o >> 4, rem = o & 15;
            int j = rem >> 2, pc = rem & 3;
            float s = bias[256 + j];
#pragma unroll
            for (int r8 = 0; r8 < 8; r8++)
                s += gp[(r8 * 32 + u) * 16 + j * 4 + pc];
            g_t[(((size_t)(b * NO + 256 + j)) << 12) + px0 + u * 4 + pc] = s;
        }
        __syncthreads();
    }

    // ---- epilogue: wmma stores (ctx bias folded into k_dwchain) ----
#pragma unroll
    for (int i = 0; i < 4; i++)
#pragma unroll
        for (int j = 0; j < 2; j++)
            wmma::store_matrix_sync(
                g_t + (((size_t)(b * NO + o0 + wm * 64 + i * 16)) << 12) + px0 + wn * 32 + j * 16,
                acc[i][j], HW, wmma::mem_row_major);
}

// =====================================================================
// K2: dw3->gelu -> dw5->gelu -> dw7->gelu chain (1 channel/CTA, 39.8KB smem),
// fast branchless gelu, all weights preloaded once. (FROZEN from R13.)
// =====================================================================
__device__ __forceinline__ float gelu_fast(float v) {
    float z  = v * 0.70710678118654752440f;
    float az = fabsf(z);
    float d  = fmaf(az, 0.3275911f, 1.0f);
    float t;  asm("rcp.approx.f32 %0,%1;" : "=f"(t) : "f"(d));
    float p  = fmaf(t, 1.061405429f, -1.453152027f);
    p = fmaf(p, t, 1.421413741f);
    p = fmaf(p, t, -0.284496736f);
    p = fmaf(p, t, 0.254829592f);
    p = p * t;
    float e;  asm("ex2.approx.f32 %0,%1;" : "=f"(e) : "f"(z * z * -1.442695040888963f));
    float er = fmaf(-p, e, 1.0f);
    er = copysignf(er, z);
    return 0.5f * v * (1.0f + er);
}

#define PST 71

template <int KS>
__device__ __forceinline__ void stage_dw(const float* __restrict__ s_in,
                                         float* __restrict__ s_out,
                                         const float* __restrict__ sW,
                                         int r, int cs) {
    const int P = KS / 2;
    float acc[16];
#pragma unroll
    for (int i = 0; i < 16; i++) acc[i] = 0.f;
#pragma unroll
    for (int dy = 0; dy < KS; dy++) {
        float row[16 + 2 * (KS / 2)];
        const float* rp = &s_in[(r + 3 + dy - P) * PST + (cs + 3 - P)];
#pragma unroll
        for (int i = 0; i < 16 + 2 * P; i++) row[i] = rp[i];
#pragma unroll
        for (int dx = 0; dx < KS; dx++) {
            float wv = sW[dy * KS + dx];
#pragma unroll
            for (int i = 0; i < 16; i++) acc[i] += row[i + dx] * wv;
        }
    }
    float* op = &s_out[(r + 3) * PST + cs + 3];
#pragma unroll
    for (int i = 0; i < 16; i++) op[i] = gelu_fast(acc[i]);
}

__global__ __launch_bounds__(256) void k_dwchain(const float* __restrict__ fw3,
                                                 const float* __restrict__ fw5,
                                                 const float* __restrict__ fw7,
                                                 const float* __restrict__ cb) {
    __shared__ float sA[70 * PST];
    __shared__ float sB[70 * PST];
    __shared__ float sW3[9], sW5[25], sW7[49];
    __shared__ float sRed[8];
    const int tid = threadIdx.x;
    const int b  = blockIdx.x >> 8;
    const int ch = blockIdx.x & 255;
    const int wrp  = tid >> 5;
    const int lane = tid & 31;
    const int lr = lane >> 1, lc = lane & 1;
    const int r  = (wrp & 3) * 16 + lr;
    const int cs = (((wrp >> 2) << 1) + lc) << 4;

    for (int i = tid; i < 70 * PST; i += 256) { sA[i] = 0.f; sB[i] = 0.f; }
    if (tid < 9) sW3[tid] = fw3[ch * 9 + tid];
    else if (tid < 34) sW5[tid - 9] = fw5[ch * 25 + tid - 9];
    else if (tid < 83) sW7[tid - 34] = fw7[ch * 49 + tid - 34];
    __syncthreads();

    const float bv = cb[ch];
    const float* src = &g_t[(size_t)(b * NO + ch) << 12];
#pragma unroll
    for (int i = 0; i < 16; i++) {
        int idx = tid + i * 256;
        int rr = idx >> 6, cc = idx & 63;
        sA[(rr + 3) * PST + cc + 3] = src[idx] + bv;
    }
    __syncthreads();

    const float* gbase = &g_t[(size_t)(b * NO + C) << 12];
    float accAll[16];
#pragma unroll
    for (int i = 0; i < 16; i++) accAll[i] = 0.f;

    stage_dw<3>(sA, sB, sW3, r, cs);
#pragma unroll
    for (int f = 0; f < 4; f++) {
        float4 gv = *(const float4*)(gbase + r * 64 + cs + f * 4);
        accAll[f * 4 + 0] += sB[(r + 3) * PST + cs + 3 + f * 4 + 0] * gv.x;
        accAll[f * 4 + 1] += sB[(r + 3) * PST + cs + 3 + f * 4 + 1] * gv.y;
        accAll[f * 4 + 2] += sB[(r + 3) * PST + cs + 3 + f * 4 + 2] * gv.z;
        accAll[f * 4 + 3] += sB[(r + 3) * PST + cs + 3 + f * 4 + 3] * gv.w;
    }
    __syncthreads();
    stage_dw<5>(sB, sA, sW5, r, cs);
#pragma unroll
    for (int f = 0; f < 4; f++) {
        float4 gv = *(const float4*)(gbase + HW + r * 64 + cs + f * 4);
        accAll[f * 4 + 0] += sA[(r + 3) * PST + cs + 3 + f * 4 + 0] * gv.x;
        accAll[f * 4 + 1] += sA[(r + 3) * PST + cs + 3 + f * 4 + 1] * gv.y;
        accAll[f * 4 + 2] += sA[(r + 3) * PST + cs + 3 + f * 4 + 2] * gv.z;
        accAll[f * 4 + 3] += sA[(r + 3) * PST + cs + 3 + f * 4 + 3] * gv.w;
    }
    __syncthreads();
    stage_dw<7>(sA, sB, sW7, r, cs);
    float lsum = 0.f;
#pragma unroll
    for (int f = 0; f < 4; f++) {
        float4 gv = *(const float4*)(gbase + 2 * HW + r * 64 + cs + f * 4);
        float v0 = sB[(r + 3) * PST + cs + 3 + f * 4 + 0];
        float v1 = sB[(r + 3) * PST + cs + 3 + f * 4 + 1];
        float v2 = sB[(r + 3) * PST + cs + 3 + f * 4 + 2];
        float v3 = sB[(r + 3) * PST + cs + 3 + f * 4 + 3];
        accAll[f * 4 + 0] += v0 * gv.x;
        accAll[f * 4 + 1] += v1 * gv.y;
        accAll[f * 4 + 2] += v2 * gv.z;
        accAll[f * 4 + 3] += v3 * gv.w;
        lsum += v0 + v1 + v2 + v3;
    }
    for (int off = 16; off; off >>= 1)
        lsum += __shfl_xor_sync(0xffffffffu, lsum, off);
    if ((tid & 31) == 0) sRed[tid >> 5] = lsum;
    __syncthreads();
    float tot = 0.f;
#pragma unroll
    for (int i = 0; i < 8; i++) tot += sRed[i];
    const float mean = tot * (1.f / 4096.f);

    float* dst = &g_ctxall[((size_t)(b * C + ch) << 12) + r * 64 + cs];
#pragma unroll
    for (int f = 0; f < 4; f++) {
        float4 gv = *(const float4*)(gbase + 3 * HW + r * 64 + cs + f * 4);
        float4 o;
        o.x = accAll[f * 4 + 0] + mean * gv.x;
        o.y = accAll[f * 4 + 1] + mean * gv.y;
        o.z = accAll[f * 4 + 2] + mean * gv.z;
        o.w = accAll[f * 4 + 3] + mean * gv.w;
        *(float4*)&dst[f * 4] = o;
    }
}

// =====================================================================
// K3: key logits — split-channel (4 groups of 64c), 64 px per CTA
// =====================================================================
__global__ __launch_bounds__(256) void k_keylogit(const float* __restrict__ key_w,
                                                  const float* __restrict__ key_b) {
    __shared__ float kw[C];
    __shared__ float red[4][64];
    const int tid = threadIdx.x;
    kw[tid] = key_w[tid];
    __syncthreads();
    const int b   = blockIdx.x >> 6;
    const int px0 = (blockIdx.x & 63) << 6;
    const int pxi = tid & 63;
    const int q   = tid >> 6;
    const float* p = &g_ctxall[((size_t)(b * C + q * 64) << 12) + px0 + pxi];
    float acc = 0.f;
#pragma unroll 8
    for (int c = 0; c < 64; c++) acc += kw[q * 64 + c] * p[(size_t)c << 12];
    red[q][pxi] = acc;
    __syncthreads();
    if (q == 0) {
        float s = red[0][pxi] + red[1][pxi] + red[2][pxi] + red[3][pxi] + key_b[0];
        g_klog[(b << 12) + px0 + pxi] = s;
    }
}

// =====================================================================
// K4: softmax over HW per batch
// =====================================================================
__global__ __launch_bounds__(256) void k_softmax() {
    __shared__ float red[8];
    const int b = blockIdx.x, tid = threadIdx.x;
    const float* p = &g_klog[b << 12];
    float v[16];
    float m = -1e30f;
#pragma unroll
    for (int i = 0; i < 16; i++) { v[i] = p[tid + (i << 8)]; m = fmaxf(m, v[i]); }
    for (int off = 16; off; off >>= 1) m = fmaxf(m, __shfl_xor_sync(0xffffffffu, m, off));
    if ((tid & 31) == 0) red[tid >> 5] = m;
    __syncthreads();
    float bm = red[0];
#pragma unroll
    for (int i = 1; i < 8; i++) bm = fmaxf(bm, red[i]);
    __syncthreads();
    float s = 0.f;
#pragma unroll
    for (int i = 0; i < 16; i++) { v[i] = expf(v[i] - bm); s += v[i]; }
    for (int off = 16; off; off >>= 1) s += __shfl_xor_sync(0xffffffffu, s, off);
    if ((tid & 31) == 0) red[tid >> 5] = s;
    __syncthreads();
    float tot = 0.f;
#pragma unroll
    for (int i = 0; i < 8; i++) tot += red[i];
    const float inv = 1.f / tot;
    float* o = &g_k[b << 12];
#pragma unroll
    for (int i = 0; i < 16; i++) o[tid + (i << 8)] = v[i] * inv;
}

// =====================================================================
// K5: qk[b,c] = sum_n ctx_all[b,c,n] * k[b,n]  (float4 vectorized)
// =====================================================================
__global__ __launch_bounds__(256) void k_qk() {
    __shared__ float sRed[8];
    const int tid = threadIdx.x;
    const int bc = blockIdx.x;
    const float4* p  = (const float4*)&g_ctxall[(size_t)bc << 12];
    const float4* kp = (const float4*)&g_k[(bc >> 8) << 12];
    float acc = 0.f;
#pragma unroll
    for (int i = 0; i < 4; i++) {
        int n = tid + (i << 8);
        float4 a = p[n], k4 = kp[n];
        acc += a.x * k4.x + a.y * k4.y + a.z * k4.z + a.w * k4.w;
    }
    for (int off = 16; off; off >>= 1) acc += __shfl_xor_sync(0xffffffffu, acc, off);
    if ((tid & 31) == 0) sRed[tid >> 5] = acc;
    __syncthreads();
    if (tid == 0) {
        float t = 0.f;
#pragma unroll
        for (int i = 0; i < 8; i++) t += sRed[i];
        g_qk[bc] = t;
    }
}

// =====================================================================
// K6: v = v2( relu( LN( v1(qk) ) ) )
// =====================================================================
__global__ __launch_bounds__(256) void k_vmlp(const float* __restrict__ v1_w,
                                              const float* __restrict__ v1_b,
                                              const float* __restrict__ ln_w,
                                              const float* __restrict__ ln_b,
                                              const float* __restrict__ v2_w,
                                              const float* __restrict__ v2_b) {
    __shared__ float sqk[B * C];
    __shared__ float sv[B * 16];
    const int tid = threadIdx.x;
    for (int i = tid; i < B * C; i += 256) sqk[i] = g_qk[i];
    __syncthreads();
    const int b = tid >> 4, j = tid & 15;
    float acc = v1_b[j];
#pragma unroll 4
    for (int c = 0; c < C; c++) acc += v1_w[j * C + c] * sqk[b * C + c];
    float mu = acc;
    for (int off = 8; off; off >>= 1) mu += __shfl_xor_sync(0xffffffffu, mu, off);
    mu *= (1.f / 16.f);
    float d = acc - mu;
    float var = d * d;
    for (int off = 8; off; off >>= 1) var += __shfl_xor_sync(0xffffffffu, var, off);
    var *= (1.f / 16.f);
    float vn = d * rsqrtf(var + 1e-5f);
    vn = vn * ln_w[j] + ln_b[j];
    vn = fmaxf(vn, 0.f);
    sv[tid] = vn;
    __syncthreads();
    const int b2 = tid >> 4;
    const int jo = tid & 15;
#pragma unroll
    for (int i = 0; i < 16; i++) {
        int co = jo + (i << 4);
        float a = v2_b[co];
#pragma unroll
        for (int jj = 0; jj < 16; jj++) a += v2_w[co * 16 + jj] * sv[b2 * 16 + jj];
        g_v[b2 * C + co] = a;
    }
}

// =====================================================================
// K7: out = ctx_all + v (broadcast over H,W)
// =====================================================================
__global__ __launch_bounds__(256) void k_final(float* __restrict__ out) {
    const int idx4 = blockIdx.x * 256 + threadIdx.x;
    const size_t base = (size_t)idx4 << 2;
    const int bc = (int)(base >> 12);
    const float vv = g_v[bc];
    float4 t = *(const float4*)&g_ctxall[base];
    t.x += vv; t.y += vv; t.z += vv; t.w += vv;
    *(float4*)&out[base] = t;
}

// =====================================================================
extern "C" void kernel_launch(void* const* d_in, const int* in_sizes, int n_in,
                              void* d_out, int out_size) {
    const float* x      = (const float*)d_in[0];
    const float* conv_w = (const float*)d_in[1];
    const float* conv_b = (const float*)d_in[2];
    const float* fw3    = (const float*)d_in[3];
    const float* fw5    = (const float*)d_in[4];
    const float* fw7    = (const float*)d_in[5];
    const float* key_w  = (const float*)d_in[6];
    const float* key_b  = (const float*)d_in[7];
    const float* v1_w   = (const float*)d_in[8];
    const float* v1_b   = (const float*)d_in[9];
    const float* ln_w   = (const float*)d_in[10];
    const float* ln_b   = (const float*)d_in[11];
    const float* v2_w   = (const float*)d_in[12];
    const float* v2_b   = (const float*)d_in[13];

    static bool attr_set = false;
    if (!attr_set) {
        cudaFuncSetAttribute(k_gemm, cudaFuncAttributeMaxDynamicSharedMemorySize, GEMM_SMEM);
        attr_set = true;
    }

    k_whalf<<<256, 256>>>(conv_w);
    k_gemm<<<1024, 256, GEMM_SMEM>>>(x, conv_w, conv_b);
    k_dwchain<<<4096, 256>>>(fw3, fw5, fw7, conv_b);
    k_keylogit<<<1024, 256>>>(key_w, key_b);
    k_softmax<<<16, 256>>>();
    k_qk<<<4096, 256>>>();
    k_vmlp<<<1, 256>>>(v1_w, v1_b, ln_w, ln_b, v2_w, v2_b);
    k_final<<<16384, 256>>>((float*)d_out);
}

// round 15
// speedup vs baseline: 1.2258x; 1.2258x over previous
#include <cuda_runtime.h>
#include <cuda_fp16.h>
#include <mma.h>
#include <math.h>
#include <stdint.h>

using namespace nvcuda;

#define HW   4096
#define WD   64
#define C    256
#define B    16
#define NO   260   // 256 ctx channels + 4 gate channels

// ---------------- scratch (static device globals; no allocs) ----------------
__device__ float g_t[B * NO * HW];       // conv1x1 output: ctx(256, no bias) + gates(4, biased)
__device__ float g_ctxall[B * C * HW];   // ctx_all
__device__ float g_klog[B * HW];
__device__ float g_k[B * HW];
__device__ float g_qk[B * C];
__device__ float g_v[B * C];
__device__ __align__(16) __half g_wh[C * C];   // w in fp16 (ctx rows)

// ---------------- cp.async helpers -----------------------------------------
__device__ __forceinline__ unsigned s2u(const void* p) {
    return (unsigned)__cvta_generic_to_shared(p);
}
__device__ __forceinline__ void cp16(unsigned dst, const void* src) {
    asm volatile("cp.async.ca.shared.global [%0], [%1], 16;" :: "r"(dst), "l"(src));
}
#define CP_COMMIT() asm volatile("cp.async.commit_group;")
#define CP_WAIT1()  asm volatile("cp.async.wait_group 1;")

// =====================================================================
// K0: convert w (ctx rows 0..255) to fp16
// =====================================================================
__global__ __launch_bounds__(256) void k_whalf(const float* __restrict__ w) {
    int idx = blockIdx.x * 256 + threadIdx.x;   // grid 256 -> 65536
    g_wh[idx] = __float2half(w[idx]);
}

// =====================================================================
// K1: wmma fp16 GEMM (single product; rel-err ~1e-4, inside budget),
// in-kernel x->fp16 conversion, + FUSED gates on oh==0 CTAs.
// __launch_bounds__(256,2): 128 regs/thread — NO spills (R14's (256,3)
// capped at 84 regs and spilled the accumulators into the mainloop).
// =====================================================================
#define BUF_ELEMS 9472
#define OFF_B 5120
#define GEMM_SMEM (2 * BUF_ELEMS * 2)   // 37888 bytes

__global__ __launch_bounds__(256, 2) void k_gemm(const float* __restrict__ x,
                                                 const float* __restrict__ w,
                                                 const float* __restrict__ bias) {
    extern __shared__ __align__(16) __half sm[];
    __shared__ float sgw[C][4];
    const int tid = threadIdx.x;
    const int wid = tid >> 5;
    const int bx = blockIdx.x;
    const int pw = bx & 31, oh = (bx >> 5) & 1, b = bx >> 6;
    const int px0 = pw << 7, o0 = oh << 7;
    const int wm = wid & 1, wn = wid >> 1;   // warp tile 64x32

    wmma::fragment<wmma::accumulator, 16, 16, 16, float> acc[4][2];
#pragma unroll
    for (int i = 0; i < 4; i++)
#pragma unroll
        for (int j = 0; j < 2; j++) wmma::fill_fragment(acc[i][j], 0.f);

    float4 gacc[4];
#pragma unroll
    for (int j = 0; j < 4; j++) gacc[j] = make_float4(0.f, 0.f, 0.f, 0.f);
    if (oh == 0) {
#pragma unroll
        for (int it = 0; it < 4; it++) {
            int i = tid + it * 256;
            sgw[i >> 2][i & 3] = w[(256 + (i & 3)) * C + (i >> 2)];
        }
    }

    auto stageA = [&](int ci) {
        unsigned base = s2u(sm + (ci & 1) * BUF_ELEMS);
        const int k0 = ci << 5;
#pragma unroll
        for (int it = 0; it < 2; it++) {
            int idx = tid + it * 256;            // 0..511: 128o x 4 groups of 8 halfs
            int o = idx >> 2, u = idx & 3;
            cp16(base + (unsigned)((o * 40 + u * 8) * 2),
                 g_wh + (o0 + o) * 256 + k0 + u * 8);
        }
    };
    auto ldx = [&](float4* R, int ci) {
        const int k0 = ci << 5;
#pragma unroll
        for (int it = 0; it < 4; it++) {
            int fi = it * 256 + tid;
            int k = fi >> 5, u = fi & 31;
            R[it] = *(const float4*)(x + (((size_t)(b * C + k0 + k)) << 12) + px0 + u * 4);
        }
    };
    auto stsB = [&](const float4* R, int ci) {
        __half* bp = sm + (ci & 1) * BUF_ELEMS;
#pragma unroll
        for (int it = 0; it < 4; it++) {
            int fi = it * 256 + tid;
            int k = fi >> 5, u = fi & 31;
            float4 v = R[it];
            __half2 h0 = __floats2half2_rn(v.x, v.y);
            __half2 h1 = __floats2half2_rn(v.z, v.w);
            uint2 hv = {*(uint32_t*)&h0, *(uint32_t*)&h1};
            *(uint2*)(bp + OFF_B + k * 136 + u * 4) = hv;
            if (oh == 0) {
                int c = (ci << 5) + k;
#pragma unroll
                for (int j = 0; j < 4; j++) {
                    float gw = sgw[c][j];
                    gacc[j].x = fmaf(gw, v.x, gacc[j].x);
                    gacc[j].y = fmaf(gw, v.y, gacc[j].y);
                    gacc[j].z = fmaf(gw, v.z, gacc[j].z);
                    gacc[j].w = fmaf(gw, v.w, gacc[j].w);
                }
            }
        }
    };
    auto compute = [&](int ci) {
        const __half* bufp = sm + (ci & 1) * BUF_ELEMS;
        const __half* A = bufp;
        const __half* Bt = bufp + OFF_B;
#pragma unroll
        for (int kk = 0; kk < 2; kk++) {
            wmma::fragment<wmma::matrix_a, 16, 16, 16, __half, wmma::row_major> af[4];
            wmma::fragment<wmma::matrix_b, 16, 16, 16, __half, wmma::row_major> bf[2];
#pragma unroll
            for (int j = 0; j < 2; j++)
                wmma::load_matrix_sync(bf[j], Bt + kk * 16 * 136 + wn * 32 + j * 16, 136);
#pragma unroll
            for (int i = 0; i < 4; i++)
                wmma::load_matrix_sync(af[i], A + (wm * 64 + i * 16) * 40 + kk * 16, 40);
#pragma unroll
            for (int i = 0; i < 4; i++)
#pragma unroll
                for (int j = 0; j < 2; j++)
                    wmma::mma_sync(acc[i][j], af[i], bf[j], acc[i][j]);
        }
    };

    float4 R[4];
    stageA(0);
    CP_COMMIT();
    ldx(R, 0);
    __syncthreads();
    for (int ci = 0; ci < 8; ci++) {
        if (ci < 7) stageA(ci + 1);
        CP_COMMIT();
        CP_WAIT1();
        stsB(R, ci);
        __syncthreads();
        if (ci < 7) ldx(R, ci + 1);
        compute(ci);
        __syncthreads();
    }

    // ---- gate reduce + store (oh==0 only; smem buffer is dead now) ----
    if (oh == 0) {
        float* gp = (float*)sm;
#pragma unroll
        for (int j = 0; j < 4; j++)
            *(float4*)(gp + tid * 16 + j * 4) = gacc[j];
        __syncthreads();
#pragma unroll
        for (int t = 0; t < 2; t++) {
            int o = tid + t * 256;
            int u = o >> 4, rem = o & 15;
            int j = rem >> 2, pc = rem & 3;
            float s = bias[256 + j];
#pragma unroll
            for (int r8 = 0; r8 < 8; r8++)
                s += gp[(r8 * 32 + u) * 16 + j * 4 + pc];
            g_t[(((size_t)(b * NO + 256 + j)) << 12) + px0 + u * 4 + pc] = s;
        }
        __syncthreads();
    }

    // ---- epilogue: wmma stores (ctx bias folded into k_dwchain) ----
#pragma unroll
    for (int i = 0; i < 4; i++)
#pragma unroll
        for (int j = 0; j < 2; j++)
            wmma::store_matrix_sync(
                g_t + (((size_t)(b * NO + o0 + wm * 64 + i * 16)) << 12) + px0 + wn * 32 + j * 16,
                acc[i][j], HW, wmma::mem_row_major);
}

// =====================================================================
// K2: dw3->gelu -> dw5->gelu -> dw7->gelu chain (1 channel/CTA, 39.8KB smem),
// fast branchless gelu, all weights preloaded once. (FROZEN.)
// =====================================================================
__device__ __forceinline__ float gelu_fast(float v) {
    float z  = v * 0.70710678118654752440f;
    float az = fabsf(z);
    float d  = fmaf(az, 0.3275911f, 1.0f);
    float t;  asm("rcp.approx.f32 %0,%1;" : "=f"(t) : "f"(d));
    float p  = fmaf(t, 1.061405429f, -1.453152027f);
    p = fmaf(p, t, 1.421413741f);
    p = fmaf(p, t, -0.284496736f);
    p = fmaf(p, t, 0.254829592f);
    p = p * t;
    float e;  asm("ex2.approx.f32 %0,%1;" : "=f"(e) : "f"(z * z * -1.442695040888963f));
    float er = fmaf(-p, e, 1.0f);
    er = copysignf(er, z);
    return 0.5f * v * (1.0f + er);
}

#define PST 71

template <int KS>
__device__ __forceinline__ void stage_dw(const float* __restrict__ s_in,
                                         float* __restrict__ s_out,
                                         const float* __restrict__ sW,
                                         int r, int cs) {
    const int P = KS / 2;
    float acc[16];
#pragma unroll
    for (int i = 0; i < 16; i++) acc[i] = 0.f;
#pragma unroll
    for (int dy = 0; dy < KS; dy++) {
        float row[16 + 2 * (KS / 2)];
        const float* rp = &s_in[(r + 3 + dy - P) * PST + (cs + 3 - P)];
#pragma unroll
        for (int i = 0; i < 16 + 2 * P; i++) row[i] = rp[i];
#pragma unroll
        for (int dx = 0; dx < KS; dx++) {
            float wv = sW[dy * KS + dx];
#pragma unroll
            for (int i = 0; i < 16; i++) acc[i] += row[i + dx] * wv;
        }
    }
    float* op = &s_out[(r + 3) * PST + cs + 3];
#pragma unroll
    for (int i = 0; i < 16; i++) op[i] = gelu_fast(acc[i]);
}

__global__ __launch_bounds__(256) void k_dwchain(const float* __restrict__ fw3,
                                                 const float* __restrict__ fw5,
                                                 const float* __restrict__ fw7,
                                                 const float* __restrict__ cb) {
    __shared__ float sA[70 * PST];
    __shared__ float sB[70 * PST];
    __shared__ float sW3[9], sW5[25], sW7[49];
    __shared__ float sRed[8];
    const int tid = threadIdx.x;
    const int b  = blockIdx.x >> 8;
    const int ch = blockIdx.x & 255;
    const int wrp  = tid >> 5;
    const int lane = tid & 31;
    const int lr = lane >> 1, lc = lane & 1;
    const int r  = (wrp & 3) * 16 + lr;
    const int cs = (((wrp >> 2) << 1) + lc) << 4;

    for (int i = tid; i < 70 * PST; i += 256) { sA[i] = 0.f; sB[i] = 0.f; }
    if (tid < 9) sW3[tid] = fw3[ch * 9 + tid];
    else if (tid < 34) sW5[tid - 9] = fw5[ch * 25 + tid - 9];
    else if (tid < 83) sW7[tid - 34] = fw7[ch * 49 + tid - 34];
    __syncthreads();

    const float bv = cb[ch];
    const float* src = &g_t[(size_t)(b * NO + ch) << 12];
#pragma unroll
    for (int i = 0; i < 16; i++) {
        int idx = tid + i * 256;
        int rr = idx >> 6, cc = idx & 63;
        sA[(rr + 3) * PST + cc + 3] = src[idx] + bv;
    }
    __syncthreads();

    const float* gbase = &g_t[(size_t)(b * NO + C) << 12];
    float accAll[16];
#pragma unroll
    for (int i = 0; i < 16; i++) accAll[i] = 0.f;

    stage_dw<3>(sA, sB, sW3, r, cs);
#pragma unroll
    for (int f = 0; f < 4; f++) {
        float4 gv = *(const float4*)(gbase + r * 64 + cs + f * 4);
        accAll[f * 4 + 0] += sB[(r + 3) * PST + cs + 3 + f * 4 + 0] * gv.x;
        accAll[f * 4 + 1] += sB[(r + 3) * PST + cs + 3 + f * 4 + 1] * gv.y;
        accAll[f * 4 + 2] += sB[(r + 3) * PST + cs + 3 + f * 4 + 2] * gv.z;
        accAll[f * 4 + 3] += sB[(r + 3) * PST + cs + 3 + f * 4 + 3] * gv.w;
    }
    __syncthreads();
    stage_dw<5>(sB, sA, sW5, r, cs);
#pragma unroll
    for (int f = 0; f < 4; f++) {
        float4 gv = *(const float4*)(gbase + HW + r * 64 + cs + f * 4);
        accAll[f * 4 + 0] += sA[(r + 3) * PST + cs + 3 + f * 4 + 0] * gv.x;
        accAll[f * 4 + 1] += sA[(r + 3) * PST + cs + 3 + f * 4 + 1] * gv.y;
        accAll[f * 4 + 2] += sA[(r + 3) * PST + cs + 3 + f * 4 + 2] * gv.z;
        accAll[f * 4 + 3] += sA[(r + 3) * PST + cs + 3 + f * 4 + 3] * gv.w;
    }
    __syncthreads();
    stage_dw<7>(sA, sB, sW7, r, cs);
    float lsum = 0.f;
#pragma unroll
    for (int f = 0; f < 4; f++) {
        float4 gv = *(const float4*)(gbase + 2 * HW + r * 64 + cs + f * 4);
        float v0 = sB[(r + 3) * PST + cs + 3 + f * 4 + 0];
        float v1 = sB[(r + 3) * PST + cs + 3 + f * 4 + 1];
        float v2 = sB[(r + 3) * PST + cs + 3 + f * 4 + 2];
        float v3 = sB[(r + 3) * PST + cs + 3 + f * 4 + 3];
        accAll[f * 4 + 0] += v0 * gv.x;
        accAll[f * 4 + 1] += v1 * gv.y;
        accAll[f * 4 + 2] += v2 * gv.z;
        accAll[f * 4 + 3] += v3 * gv.w;
        lsum += v0 + v1 + v2 + v3;
    }
    for (int off = 16; off; off >>= 1)
        lsum += __shfl_xor_sync(0xffffffffu, lsum, off);
    if ((tid & 31) == 0) sRed[tid >> 5] = lsum;
    __syncthreads();
    float tot = 0.f;
#pragma unroll
    for (int i = 0; i < 8; i++) tot += sRed[i];
    const float mean = tot * (1.f / 4096.f);

    float* dst = &g_ctxall[((size_t)(b * C + ch) << 12) + r * 64 + cs];
#pragma unroll
    for (int f = 0; f < 4; f++) {
        float4 gv = *(const float4*)(gbase + 3 * HW + r * 64 + cs + f * 4);
        float4 o;
        o.x = accAll[f * 4 + 0] + mean * gv.x;
        o.y = accAll[f * 4 + 1] + mean * gv.y;
        o.z = accAll[f * 4 + 2] + mean * gv.z;
        o.w = accAll[f * 4 + 3] + mean * gv.w;
        *(float4*)&dst[f * 4] = o;
    }
}

// =====================================================================
// K3: key logits — split-channel (4 groups of 64c), 64 px per CTA
// =====================================================================
__global__ __launch_bounds__(256) void k_keylogit(const float* __restrict__ key_w,
                                                  const float* __restrict__ key_b) {
    __shared__ float kw[C];
    __shared__ float red[4][64];
    const int tid = threadIdx.x;
    kw[tid] = key_w[tid];
    __syncthreads();
    const int b   = blockIdx.x >> 6;
    const int px0 = (blockIdx.x & 63) << 6;
    const int pxi = tid & 63;
    const int q   = tid >> 6;
    const float* p = &g_ctxall[((size_t)(b * C + q * 64) << 12) + px0 + pxi];
    float acc = 0.f;
#pragma unroll 8
    for (int c = 0; c < 64; c++) acc += kw[q * 64 + c] * p[(size_t)c << 12];
    red[q][pxi] = acc;
    __syncthreads();
    if (q == 0) {
        float s = red[0][pxi] + red[1][pxi] + red[2][pxi] + red[3][pxi] + key_b[0];
        g_klog[(b << 12) + px0 + pxi] = s;
    }
}

// =====================================================================
// K4: softmax over HW per batch
// =====================================================================
__global__ __launch_bounds__(256) void k_softmax() {
    __shared__ float red[8];
    const int b = blockIdx.x, tid = threadIdx.x;
    const float* p = &g_klog[b << 12];
    float v[16];
    float m = -1e30f;
#pragma unroll
    for (int i = 0; i < 16; i++) { v[i] = p[tid + (i << 8)]; m = fmaxf(m, v[i]); }
    for (int off = 16; off; off >>= 1) m = fmaxf(m, __shfl_xor_sync(0xffffffffu, m, off));
    if ((tid & 31) == 0) red[tid >> 5] = m;
    __syncthreads();
    float bm = red[0];
#pragma unroll
    for (int i = 1; i < 8; i++) bm = fmaxf(bm, red[i]);
    __syncthreads();
    float s = 0.f;
#pragma unroll
    for (int i = 0; i < 16; i++) { v[i] = expf(v[i] - bm); s += v[i]; }
    for (int off = 16; off; off >>= 1) s += __shfl_xor_sync(0xffffffffu, s, off);
    if ((tid & 31) == 0) red[tid >> 5] = s;
    __syncthreads();
    float tot = 0.f;
#pragma unroll
    for (int i = 0; i < 8; i++) tot += red[i];
    const float inv = 1.f / tot;
    float* o = &g_k[b << 12];
#pragma unroll
    for (int i = 0; i < 16; i++) o[tid + (i << 8)] = v[i] * inv;
}

// =====================================================================
// K5: qk[b,c] = sum_n ctx_all[b,c,n] * k[b,n]  (float4 vectorized)
// =====================================================================
__global__ __launch_bounds__(256) void k_qk() {
    __shared__ float sRed[8];
    const int tid = threadIdx.x;
    const int bc = blockIdx.x;
    const float4* p  = (const float4*)&g_ctxall[(size_t)bc << 12];
    const float4* kp = (const float4*)&g_k[(bc >> 8) << 12];
    float acc = 0.f;
#pragma unroll
    for (int i = 0; i < 4; i++) {
        int n = tid + (i << 8);
        float4 a = p[n], k4 = kp[n];
        acc += a.x * k4.x + a.y * k4.y + a.z * k4.z + a.w * k4.w;
    }
    for (int off = 16; off; off >>= 1) acc += __shfl_xor_sync(0xffffffffu, acc, off);
    if ((tid & 31) == 0) sRed[tid >> 5] = acc;
    __syncthreads();
    if (tid == 0) {
        float t = 0.f;
#pragma unroll
        for (int i = 0; i < 8; i++) t += sRed[i];
        g_qk[bc] = t;
    }
}

// =====================================================================
// K6: v = v2( relu( LN( v1(qk) ) ) )
// =====================================================================
__global__ __launch_bounds__(256) void k_vmlp(const float* __restrict__ v1_w,
                                              const float* __restrict__ v1_b,
                                              const float* __restrict__ ln_w,
                                              const float* __restrict__ ln_b,
                                              const float* __restrict__ v2_w,
                                              const float* __restrict__ v2_b) {
    __shared__ float sqk[B * C];
    __shared__ float sv[B * 16];
    const int tid = threadIdx.x;
    for (int i = tid; i < B * C; i += 256) sqk[i] = g_qk[i];
    __syncthreads();
    const int b = tid >> 4, j = tid & 15;
    float acc = v1_b[j];
#pragma unroll 4
    for (int c = 0; c < C; c++) acc += v1_w[j * C + c] * sqk[b * C + c];
    float mu = acc;
    for (int off = 8; off; off >>= 1) mu += __shfl_xor_sync(0xffffffffu, mu, off);
    mu *= (1.f / 16.f);
    float d = acc - mu;
    float var = d * d;
    for (int off = 8; off; off >>= 1) var += __shfl_xor_sync(0xffffffffu, var, off);
    var *= (1.f / 16.f);
    float vn = d * rsqrtf(var + 1e-5f);
    vn = vn * ln_w[j] + ln_b[j];
    vn = fmaxf(vn, 0.f);
    sv[tid] = vn;
    __syncthreads();
    const int b2 = tid >> 4;
    const int jo = tid & 15;
#pragma unroll
    for (int i = 0; i < 16; i++) {
        int co = jo + (i << 4);
        float a = v2_b[co];
#pragma unroll
        for (int jj = 0; jj < 16; jj++) a += v2_w[co * 16 + jj] * sv[b2 * 16 + jj];
        g_v[b2 * C + co] = a;
    }
}

// =====================================================================
// K7: out = ctx_all + v (broadcast over H,W)
// =====================================================================
__global__ __launch_bounds__(256) void k_final(float* __restrict__ out) {
    const int idx4 = blockIdx.x * 256 + threadIdx.x;
    const size_t base = (size_t)idx4 << 2;
    const int bc = (int)(base >> 12);
    const float vv = g_v[bc];
    float4 t = *(const float4*)&g_ctxall[base];
    t.x += vv; t.y += vv; t.z += vv; t.w += vv;
    *(float4*)&out[base] = t;
}

// =====================================================================
extern "C" void kernel_launch(void* const* d_in, const int* in_sizes, int n_in,
                              void* d_out, int out_size) {
    const float* x      = (const float*)d_in[0];
    const float* conv_w = (const float*)d_in[1];
    const float* conv_b = (const float*)d_in[2];
    const float* fw3    = (const float*)d_in[3];
    const float* fw5    = (const float*)d_in[4];
    const float* fw7    = (const float*)d_in[5];
    const float* key_w  = (const float*)d_in[6];
    const float* key_b  = (const float*)d_in[7];
    const float* v1_w   = (const float*)d_in[8];
    const float* v1_b   = (const float*)d_in[9];
    const float* ln_w   = (const float*)d_in[10];
    const float* ln_b   = (const float*)d_in[11];
    const float* v2_w   = (const float*)d_in[12];
    const float* v2_b   = (const float*)d_in[13];

    static bool attr_set = false;
    if (!attr_set) {
        cudaFuncSetAttribute(k_gemm, cudaFuncAttributeMaxDynamicSharedMemorySize, GEMM_SMEM);
        attr_set = true;
    }

    k_whalf<<<256, 256>>>(conv_w);
    k_gemm<<<1024, 256, GEMM_SMEM>>>(x, conv_w, conv_b);
    k_dwchain<<<4096, 256>>>(fw3, fw5, fw7, conv_b);
    k_keylogit<<<1024, 256>>>(key_w, key_b);
    k_softmax<<<16, 256>>>();
    k_qk<<<4096, 256>>>();
    k_vmlp<<<1, 256>>>(v1_w, v1_b, ln_w, ln_b, v2_w, v2_b);
    k_final<<<16384, 256>>>((float*)d_out);
}

// round 16
// speedup vs baseline: 1.2870x; 1.0499x over previous
#include <cuda_runtime.h>
#include <cuda_fp16.h>
#include <mma.h>
#include <math.h>
#include <stdint.h>

using namespace nvcuda;

#define HW   4096
#define WD   64
#define C    256
#define B    16
#define NO   260   // 256 ctx channels + 4 gate channels

// ---------------- scratch (static device globals; no allocs) ----------------
__device__ float g_t[B * NO * HW];       // conv1x1 output: ctx(256, no bias) + gates(4, biased)
__device__ float g_ctxall[B * C * HW];   // ctx_all
__device__ float g_klog[B * HW];
__device__ float g_k[B * HW];
__device__ float g_qk[B * C];
__device__ float g_v[B * C];
__device__ __align__(16) __half g_wh[C * C];   // w in fp16 (ctx rows)

// ---------------- cp.async helpers -----------------------------------------
__device__ __forceinline__ unsigned s2u(const void* p) {
    return (unsigned)__cvta_generic_to_shared(p);
}
__device__ __forceinline__ void cp16(unsigned dst, const void* src) {
    asm volatile("cp.async.ca.shared.global [%0], [%1], 16;" :: "r"(dst), "l"(src));
}
#define CP_COMMIT() asm volatile("cp.async.commit_group;")
#define CP_WAIT1()  asm volatile("cp.async.wait_group 1;")

// =====================================================================
// K0: convert w (ctx rows 0..255) to fp16
// =====================================================================
__global__ __launch_bounds__(256) void k_whalf(const float* __restrict__ w) {
    int idx = blockIdx.x * 256 + threadIdx.x;
    g_wh[idx] = __float2half(w[idx]);
}

// =====================================================================
// K1: wmma fp16 GEMM (single product), in-kernel x->fp16 conversion,
// + FUSED gates on oh==0 CTAs. launch_bounds(256,2): no spills. (FROZEN)
// =====================================================================
#define BUF_ELEMS 9472
#define OFF_B 5120
#define GEMM_SMEM (2 * BUF_ELEMS * 2)   // 37888 bytes

__global__ __launch_bounds__(256, 2) void k_gemm(const float* __restrict__ x,
                                                 const float* __restrict__ w,
                                                 const float* __restrict__ bias) {
    extern __shared__ __align__(16) __half sm[];
    __shared__ float sgw[C][4];
    const int tid = threadIdx.x;
    const int wid = tid >> 5;
    const int bx = blockIdx.x;
    const int pw = bx & 31, oh = (bx >> 5) & 1, b = bx >> 6;
    const int px0 = pw << 7, o0 = oh << 7;
    const int wm = wid & 1, wn = wid >> 1;

    wmma::fragment<wmma::accumulator, 16, 16, 16, float> acc[4][2];
#pragma unroll
    for (int i = 0; i < 4; i++)
#pragma unroll
        for (int j = 0; j < 2; j++) wmma::fill_fragment(acc[i][j], 0.f);

    float4 gacc[4];
#pragma unroll
    for (int j = 0; j < 4; j++) gacc[j] = make_float4(0.f, 0.f, 0.f, 0.f);
    if (oh == 0) {
#pragma unroll
        for (int it = 0; it < 4; it++) {
            int i = tid + it * 256;
            sgw[i >> 2][i & 3] = w[(256 + (i & 3)) * C + (i >> 2)];
        }
    }

    auto stageA = [&](int ci) {
        unsigned base = s2u(sm + (ci & 1) * BUF_ELEMS);
        const int k0 = ci << 5;
#pragma unroll
        for (int it = 0; it < 2; it++) {
            int idx = tid + it * 256;
            int o = idx >> 2, u = idx & 3;
            cp16(base + (unsigned)((o * 40 + u * 8) * 2),
                 g_wh + (o0 + o) * 256 + k0 + u * 8);
        }
    };
    auto ldx = [&](float4* R, int ci) {
        const int k0 = ci << 5;
#pragma unroll
        for (int it = 0; it < 4; it++) {
            int fi = it * 256 + tid;
            int k = fi >> 5, u = fi & 31;
            R[it] = *(const float4*)(x + (((size_t)(b * C + k0 + k)) << 12) + px0 + u * 4);
        }
    };
    auto stsB = [&](const float4* R, int ci) {
        __half* bp = sm + (ci & 1) * BUF_ELEMS;
#pragma unroll
        for (int it = 0; it < 4; it++) {
            int fi = it * 256 + tid;
            int k = fi >> 5, u = fi & 31;
            float4 v = R[it];
            __half2 h0 = __floats2half2_rn(v.x, v.y);
            __half2 h1 = __floats2half2_rn(v.z, v.w);
            uint2 hv = {*(uint32_t*)&h0, *(uint32_t*)&h1};
            *(uint2*)(bp + OFF_B + k * 136 + u * 4) = hv;
            if (oh == 0) {
                int c = (ci << 5) + k;
#pragma unroll
                for (int j = 0; j < 4; j++) {
                    float gw = sgw[c][j];
                    gacc[j].x = fmaf(gw, v.x, gacc[j].x);
                    gacc[j].y = fmaf(gw, v.y, gacc[j].y);
                    gacc[j].z = fmaf(gw, v.z, gacc[j].z);
                    gacc[j].w = fmaf(gw, v.w, gacc[j].w);
                }
            }
        }
    };
    auto compute = [&](int ci) {
        const __half* bufp = sm + (ci & 1) * BUF_ELEMS;
        const __half* A = bufp;
        const __half* Bt = bufp + OFF_B;
#pragma unroll
        for (int kk = 0; kk < 2; kk++) {
            wmma::fragment<wmma::matrix_a, 16, 16, 16, __half, wmma::row_major> af[4];
            wmma::fragment<wmma::matrix_b, 16, 16, 16, __half, wmma::row_major> bf[2];
#pragma unroll
            for (int j = 0; j < 2; j++)
                wmma::load_matrix_sync(bf[j], Bt + kk * 16 * 136 + wn * 32 + j * 16, 136);
#pragma unroll
            for (int i = 0; i < 4; i++)
                wmma::load_matrix_sync(af[i], A + (wm * 64 + i * 16) * 40 + kk * 16, 40);
#pragma unroll
            for (int i = 0; i < 4; i++)
#pragma unroll
                for (int j = 0; j < 2; j++)
                    wmma::mma_sync(acc[i][j], af[i], bf[j], acc[i][j]);
        }
    };

    float4 R[4];
    stageA(0);
    CP_COMMIT();
    ldx(R, 0);
    __syncthreads();
    for (int ci = 0; ci < 8; ci++) {
        if (ci < 7) stageA(ci + 1);
        CP_COMMIT();
        CP_WAIT1();
        stsB(R, ci);
        __syncthreads();
        if (ci < 7) ldx(R, ci + 1);
        compute(ci);
        __syncthreads();
    }

    if (oh == 0) {
        float* gp = (float*)sm;
#pragma unroll
        for (int j = 0; j < 4; j++)
            *(float4*)(gp + tid * 16 + j * 4) = gacc[j];
        __syncthreads();
#pragma unroll
        for (int t = 0; t < 2; t++) {
            int o = tid + t * 256;
            int u = o >> 4, rem = o & 15;
            int j = rem >> 2, pc = rem & 3;
            float s = bias[256 + j];
#pragma unroll
            for (int r8 = 0; r8 < 8; r8++)
                s += gp[(r8 * 32 + u) * 16 + j * 4 + pc];
            g_t[(((size_t)(b * NO + 256 + j)) << 12) + px0 + u * 4 + pc] = s;
        }
        __syncthreads();
    }

#pragma unroll
    for (int i = 0; i < 4; i++)
#pragma unroll
        for (int j = 0; j < 2; j++)
            wmma::store_matrix_sync(
                g_t + (((size_t)(b * NO + o0 + wm * 64 + i * 16)) << 12) + px0 + wn * 32 + j * 16,
                acc[i][j], HW, wmma::mem_row_major);
}

// =====================================================================
// K2: dwchain. Changes this round (all contained):
//  - 3-term A&S erf poly (abs err 2.5e-5; gelu rel err ~1e-5 << gemm 8.7e-5)
//  - gelu in place; stage outputs returned in registers -> gated accumulate
//    reads regs, not smem
//  - stage-7 result never stored to smem (pointwise consumers only)
// =====================================================================
__device__ __forceinline__ float gelu_fast(float v) {
    float z  = v * 0.70710678118654752440f;
    float az = fabsf(z);
    float d  = fmaf(az, 0.47047f, 1.0f);
    float t;  asm("rcp.approx.f32 %0,%1;" : "=f"(t) : "f"(d));
    float p  = fmaf(t, 0.7478556f, -0.0958798f);
    p = fmaf(p, t, 0.3480242f);
    p = p * t;
    float e;  asm("ex2.approx.f32 %0,%1;" : "=f"(e) : "f"(z * z * -1.442695040888963f));
    float er = fmaf(-p, e, 1.0f);            // erf(|z|)
    er = copysignf(er, z);
    return 0.5f * v * (1.0f + er);
}

#define PST 71

// conv + gelu; result left in out[16]; optionally stored to s_out (halo use)
template <int KS, bool STORE>
__device__ __forceinline__ void stage_dw(const float* __restrict__ s_in,
                                         float* __restrict__ s_out,
                                         const float* __restrict__ sW,
                                         int r, int cs, float* __restrict__ out) {
    const int P = KS / 2;
#pragma unroll
    for (int i = 0; i < 16; i++) out[i] = 0.f;
#pragma unroll
    for (int dy = 0; dy < KS; dy++) {
        float row[16 + 2 * (KS / 2)];
        const float* rp = &s_in[(r + 3 + dy - P) * PST + (cs + 3 - P)];
#pragma unroll
        for (int i = 0; i < 16 + 2 * P; i++) row[i] = rp[i];
#pragma unroll
        for (int dx = 0; dx < KS; dx++) {
            float wv = sW[dy * KS + dx];
#pragma unroll
            for (int i = 0; i < 16; i++) out[i] += row[i + dx] * wv;
        }
    }
#pragma unroll
    for (int i = 0; i < 16; i++) out[i] = gelu_fast(out[i]);
    if (STORE) {
        float* op = &s_out[(r + 3) * PST + cs + 3];
#pragma unroll
        for (int i = 0; i < 16; i++) op[i] = out[i];
    }
}

__global__ __launch_bounds__(256) void k_dwchain(const float* __restrict__ fw3,
                                                 const float* __restrict__ fw5,
                                                 const float* __restrict__ fw7,
                                                 const float* __restrict__ cb) {
    __shared__ float sA[70 * PST];
    __shared__ float sB[70 * PST];
    __shared__ float sW3[9], sW5[25], sW7[49];
    __shared__ float sRed[8];
    const int tid = threadIdx.x;
    const int b  = blockIdx.x >> 8;
    const int ch = blockIdx.x & 255;
    const int wrp  = tid >> 5;
    const int lane = tid & 31;
    const int lr = lane >> 1, lc = lane & 1;
    const int r  = (wrp & 3) * 16 + lr;
    const int cs = (((wrp >> 2) << 1) + lc) << 4;

    for (int i = tid; i < 70 * PST; i += 256) { sA[i] = 0.f; sB[i] = 0.f; }
    if (tid < 9) sW3[tid] = fw3[ch * 9 + tid];
    else if (tid < 34) sW5[tid - 9] = fw5[ch * 25 + tid - 9];
    else if (tid < 83) sW7[tid - 34] = fw7[ch * 49 + tid - 34];
    __syncthreads();

    const float bv = cb[ch];
    const float* src = &g_t[(size_t)(b * NO + ch) << 12];
#pragma unroll
    for (int i = 0; i < 16; i++) {
        int idx = tid + i * 256;
        int rr = idx >> 6, cc = idx & 63;
        sA[(rr + 3) * PST + cc + 3] = src[idx] + bv;
    }
    __syncthreads();

    const float* gbase = &g_t[(size_t)(b * NO + C) << 12];
    float accAll[16];
#pragma unroll
    for (int i = 0; i < 16; i++) accAll[i] = 0.f;
    float sv[16];

    // ---- 3x3 ----
    stage_dw<3, true>(sA, sB, sW3, r, cs, sv);
#pragma unroll
    for (int f = 0; f < 4; f++) {
        float4 gv = *(const float4*)(gbase + r * 64 + cs + f * 4);
        accAll[f * 4 + 0] += sv[f * 4 + 0] * gv.x;
        accAll[f * 4 + 1] += sv[f * 4 + 1] * gv.y;
        accAll[f * 4 + 2] += sv[f * 4 + 2] * gv.z;
        accAll[f * 4 + 3] += sv[f * 4 + 3] * gv.w;
    }
    __syncthreads();
    // ---- 5x5 ----
    stage_dw<5, true>(sB, sA, sW5, r, cs, sv);
#pragma unroll
    for (int f = 0; f < 4; f++) {
        float4 gv = *(const float4*)(gbase + HW + r * 64 + cs + f * 4);
        accAll[f * 4 + 0] += sv[f * 4 + 0] * gv.x;
        accAll[f * 4 + 1] += sv[f * 4 + 1] * gv.y;
        accAll[f * 4 + 2] += sv[f * 4 + 2] * gv.z;
        accAll[f * 4 + 3] += sv[f * 4 + 3] * gv.w;
    }
    __syncthreads();
    // ---- 7x7 (output stays in registers; no halo consumer) ----
    stage_dw<7, false>(sA, sB, sW7, r, cs, sv);
    float lsum = 0.f;
#pragma unroll
    for (int f = 0; f < 4; f++) {
        float4 gv = *(const float4*)(gbase + 2 * HW + r * 64 + cs + f * 4);
        accAll[f * 4 + 0] += sv[f * 4 + 0] * gv.x;
        accAll[f * 4 + 1] += sv[f * 4 + 1] * gv.y;
        accAll[f * 4 + 2] += sv[f * 4 + 2] * gv.z;
        accAll[f * 4 + 3] += sv[f * 4 + 3] * gv.w;
        lsum += sv[f * 4 + 0] + sv[f * 4 + 1] + sv[f * 4 + 2] + sv[f * 4 + 3];
    }
    for (int off = 16; off; off >>= 1)
        lsum += __shfl_xor_sync(0xffffffffu, lsum, off);
    if ((tid & 31) == 0) sRed[tid >> 5] = lsum;
    __syncthreads();
    float tot = 0.f;
#pragma unroll
    for (int i = 0; i < 8; i++) tot += sRed[i];
    const float mean = tot * (1.f / 4096.f);

    float* dst = &g_ctxall[((size_t)(b * C + ch) << 12) + r * 64 + cs];
#pragma unroll
    for (int f = 0; f < 4; f++) {
        float4 gv = *(const float4*)(gbase + 3 * HW + r * 64 + cs + f * 4);
        float4 o;
        o.x = accAll[f * 4 + 0] + mean * gv.x;
        o.y = accAll[f * 4 + 1] + mean * gv.y;
        o.z = accAll[f * 4 + 2] + mean * gv.z;
        o.w = accAll[f * 4 + 3] + mean * gv.w;
        *(float4*)&dst[f * 4] = o;
    }
}

// =====================================================================
// K3: key logits — split-channel (4 groups of 64c), 64 px per CTA
// =====================================================================
__global__ __launch_bounds__(256) void k_keylogit(const float* __restrict__ key_w,
                                                  const float* __restrict__ key_b) {
    __shared__ float kw[C];
    __shared__ float red[4][64];
    const int tid = threadIdx.x;
    kw[tid] = key_w[tid];
    __syncthreads();
    const int b   = blockIdx.x >> 6;
    const int px0 = (blockIdx.x & 63) << 6;
    const int pxi = tid & 63;
    const int q   = tid >> 6;
    const float* p = &g_ctxall[((size_t)(b * C + q * 64) << 12) + px0 + pxi];
    float acc = 0.f;
#pragma unroll 8
    for (int c = 0; c < 64; c++) acc += kw[q * 64 + c] * p[(size_t)c << 12];
    red[q][pxi] = acc;
    __syncthreads();
    if (q == 0) {
        float s = red[0][pxi] + red[1][pxi] + red[2][pxi] + red[3][pxi] + key_b[0];
        g_klog[(b << 12) + px0 + pxi] = s;
    }
}

// =====================================================================
// K4: softmax over HW per batch
// =====================================================================
__global__ __launch_bounds__(256) void k_softmax() {
    __shared__ float red[8];
    const int b = blockIdx.x, tid = threadIdx.x;
    const float* p = &g_klog[b << 12];
    float v[16];
    float m = -1e30f;
#pragma unroll
    for (int i = 0; i < 16; i++) { v[i] = p[tid + (i << 8)]; m = fmaxf(m, v[i]); }
    for (int off = 16; off; off >>= 1) m = fmaxf(m, __shfl_xor_sync(0xffffffffu, m, off));
    if ((tid & 31) == 0) red[tid >> 5] = m;
    __syncthreads();
    float bm = red[0];
#pragma unroll
    for (int i = 1; i < 8; i++) bm = fmaxf(bm, red[i]);
    __syncthreads();
    float s = 0.f;
#pragma unroll
    for (int i = 0; i < 16; i++) { v[i] = expf(v[i] - bm); s += v[i]; }
    for (int off = 16; off; off >>= 1) s += __shfl_xor_sync(0xffffffffu, s, off);
    if ((tid & 31) == 0) red[tid >> 5] = s;
    __syncthreads();
    float tot = 0.f;
#pragma unroll
    for (int i = 0; i < 8; i++) tot += red[i];
    const float inv = 1.f / tot;
    float* o = &g_k[b << 12];
#pragma unroll
    for (int i = 0; i < 16; i++) o[tid + (i << 8)] = v[i] * inv;
}

// =====================================================================
// K5: qk[b,c] = sum_n ctx_all[b,c,n] * k[b,n]  (float4 vectorized)
// =====================================================================
__global__ __launch_bounds__(256) void k_qk() {
    __shared__ float sRed[8];
    const int tid = threadIdx.x;
    const int bc = blockIdx.x;
    const float4* p  = (const float4*)&g_ctxall[(size_t)bc << 12];
    const float4* kp = (const float4*)&g_k[(bc >> 8) << 12];
    float acc = 0.f;
#pragma unroll
    for (int i = 0; i < 4; i++) {
        int n = tid + (i << 8);
        float4 a = p[n], k4 = kp[n];
        acc += a.x * k4.x + a.y * k4.y + a.z * k4.z + a.w * k4.w;
    }
    for (int off = 16; off; off >>= 1) acc += __shfl_xor_sync(0xffffffffu, acc, off);
    if ((tid & 31) == 0) sRed[tid >> 5] = acc;
    __syncthreads();
    if (tid == 0) {
        float t = 0.f;
#pragma unroll
        for (int i = 0; i < 8; i++) t += sRed[i];
        g_qk[bc] = t;
    }
}

// =====================================================================
// K6: v = v2( relu( LN( v1(qk) ) ) )
// =====================================================================
__global__ __launch_bounds__(256) void k_vmlp(const float* __restrict__ v1_w,
                                              const float* __restrict__ v1_b,
                                              const float* __restrict__ ln_w,
                                              const float* __restrict__ ln_b,
                                              const float* __restrict__ v2_w,
                                              const float* __restrict__ v2_b) {
    __shared__ float sqk[B * C];
    __shared__ float sv[B * 16];
    const int tid = threadIdx.x;
    for (int i = tid; i < B * C; i += 256) sqk[i] = g_qk[i];
    __syncthreads();
    const int b = tid >> 4, j = tid & 15;
    float acc = v1_b[j];
#pragma unroll 4
    for (int c = 0; c < C; c++) acc += v1_w[j * C + c] * sqk[b * C + c];
    float mu = acc;
    for (int off = 8; off; off >>= 1) mu += __shfl_xor_sync(0xffffffffu, mu, off);
    mu *= (1.f / 16.f);
    float d = acc - mu;
    float var = d * d;
    for (int off = 8; off; off >>= 1) var += __shfl_xor_sync(0xffffffffu, var, off);
    var *= (1.f / 16.f);
    float vn = d * rsqrtf(var + 1e-5f);
    vn = vn * ln_w[j] + ln_b[j];
    vn = fmaxf(vn, 0.f);
    sv[tid] = vn;
    __syncthreads();
    const int b2 = tid >> 4;
    const int jo = tid & 15;
#pragma unroll
    for (int i = 0; i < 16; i++) {
        int co = jo + (i << 4);
        float a = v2_b[co];
#pragma unroll
        for (int jj = 0; jj < 16; jj++) a += v2_w[co * 16 + jj] * sv[b2 * 16 + jj];
        g_v[b2 * C + co] = a;
    }
}

// =====================================================================
// K7: out = ctx_all + v (broadcast over H,W)
// =====================================================================
__global__ __launch_bounds__(256) void k_final(float* __restrict__ out) {
    const int idx4 = blockIdx.x * 256 + threadIdx.x;
    const size_t base = (size_t)idx4 << 2;
    const int bc = (int)(base >> 12);
    const float vv = g_v[bc];
    float4 t = *(const float4*)&g_ctxall[base];
    t.x += vv; t.y += vv; t.z += vv; t.w += vv;
    *(float4*)&out[base] = t;
}

// =====================================================================
extern "C" void kernel_launch(void* const* d_in, const int* in_sizes, int n_in,
                              void* d_out, int out_size) {
    const float* x      = (const float*)d_in[0];
    const float* conv_w = (const float*)d_in[1];
    const float* conv_b = (const float*)d_in[2];
    const float* fw3    = (const float*)d_in[3];
    const float* fw5    = (const float*)d_in[4];
    const float* fw7    = (const float*)d_in[5];
    const float* key_w  = (const float*)d_in[6];
    const float* key_b  = (const float*)d_in[7];
    const float* v1_w   = (const float*)d_in[8];
    const float* v1_b   = (const float*)d_in[9];
    const float* ln_w   = (const float*)d_in[10];
    const float* ln_b   = (const float*)d_in[11];
    const float* v2_w   = (const float*)d_in[12];
    const float* v2_b   = (const float*)d_in[13];

    static bool attr_set = false;
    if (!attr_set) {
        cudaFuncSetAttribute(k_gemm, cudaFuncAttributeMaxDynamicSharedMemorySize, GEMM_SMEM);
        attr_set = true;
    }

    k_whalf<<<256, 256>>>(conv_w);
    k_gemm<<<1024, 256, GEMM_SMEM>>>(x, conv_w, conv_b);
    k_dwchain<<<4096, 256>>>(fw3, fw5, fw7, conv_b);
    k_keylogit<<<1024, 256>>>(key_w, key_b);
    k_softmax<<<16, 256>>>();
    k_qk<<<4096, 256>>>();
    k_vmlp<<<1, 256>>>(v1_w, v1_b, ln_w, ln_b, v2_w, v2_b);
    k_final<<<16384, 256>>>((float*)d_out);
}